// round 5
// baseline (speedup 1.0000x reference)
#include <cuda_runtime.h>
#include <cuda_bf16.h>

// TELIF: temporal-encoded LIF neuron scan — single fused kernel.
//   tx : [T, B, N] float32   (T=512, B=64, N=1024)
//   TE : [N, T]    float32   (contiguous in t per neuron -> float4 per chunk)
//   out: [T, B, N] float32 spikes
//
// Per (b, n), sequential in t:
//   th = th + v*TE[n,t] - (th - THRESHOLD)*BETA
//   v  = v*DECAY*(1 - y) + x
//   y  = (v > th) ? 1 : 0

#define T_STEPS 512
#define B_DIM   64
#define N_DIM   1024
#define BN      (B_DIM * N_DIM)      // 65536
#define U       4                    // timesteps per chunk
#define NCHUNK  (T_STEPS / U)        // 128

#define REST      0.0f
#define DECAY     0.2f
#define THRESHOLD 0.3f
#define BETA      0.02f

// ---------------------------------------------------------------------------
// One thread per (b,n) chain. 8 register buffers of U=4 timesteps, prefetch
// distance 7 chunks (28 tx loads in flight), all buffer indices compile-time.
// tx streamed via __ldcs (read-once); TE loaded as one float4 per chunk from
// the thread's own contiguous row — 8 consecutive chunks share one 128B L1
// line, so TE is L1-resident with 8x reuse (no transpose kernel needed).
// ---------------------------------------------------------------------------

#define LOAD_CHUNK(xq, tq, c)                                         \
    {                                                                 \
        tq = te4[(c)];                                                \
        _Pragma("unroll")                                             \
        for (int u = 0; u < U; u++)                                   \
            xq[u] = __ldcs(&tx[((c) * U + u) * BN + g]);              \
    }

// arithmetic form identical to the rel_err==0.0 version
#define ONE_STEP(x, te, c, u)                                         \
    {                                                                 \
        th = th + v * (te) - (th - THRESHOLD) * BETA;                 \
        v  = v * DECAY * (1.0f - y) + (x);                            \
        y  = (v > th) ? 1.0f : 0.0f;                                  \
        __stcs(&ty[((c) * U + (u)) * BN + g], y);                     \
    }

#define COMPUTE_CHUNK(xq, tq, c)                                      \
    {                                                                 \
        ONE_STEP(xq[0], tq.x, c, 0)                                   \
        ONE_STEP(xq[1], tq.y, c, 1)                                   \
        ONE_STEP(xq[2], tq.z, c, 2)                                   \
        ONE_STEP(xq[3], tq.w, c, 3)                                   \
    }

__global__ void __launch_bounds__(64) telif_kernel(
    const float* __restrict__ tx,
    const float* __restrict__ TE,
    float* __restrict__ ty)
{
    const int g = blockIdx.x * blockDim.x + threadIdx.x;  // g = b*N + n
    const int n = g & (N_DIM - 1);

    // this thread's TE row: TE[n, 0..511], contiguous, float4-aligned
    const float4* te4 = reinterpret_cast<const float4*>(TE + (size_t)n * T_STEPS);

    float v  = REST;
    float y  = 0.0f;
    float th = THRESHOLD;

    float xA[U], xB[U], xC[U], xD[U], xE[U], xF[U], xG[U], xH[U];
    float4 tA, tB, tC, tD, tE_, tF, tG, tH;

    // prologue: chunks 0..6 into A..G
    LOAD_CHUNK(xA, tA, 0)
    LOAD_CHUNK(xB, tB, 1)
    LOAD_CHUNK(xC, tC, 2)
    LOAD_CHUNK(xD, tD, 3)
    LOAD_CHUNK(xE, tE_, 4)
    LOAD_CHUNK(xF, tF, 5)
    LOAD_CHUNK(xG, tG, 6)

    #pragma unroll 1
    for (int c = 0; c < NCHUNK; c += 8) {
        LOAD_CHUNK(xH, tH, c + 7)
        COMPUTE_CHUNK(xA, tA, c)
        if (c +  8 < NCHUNK) LOAD_CHUNK(xA, tA, c + 8)
        COMPUTE_CHUNK(xB, tB, c + 1)
        if (c +  9 < NCHUNK) LOAD_CHUNK(xB, tB, c + 9)
        COMPUTE_CHUNK(xC, tC, c + 2)
        if (c + 10 < NCHUNK) LOAD_CHUNK(xC, tC, c + 10)
        COMPUTE_CHUNK(xD, tD, c + 3)
        if (c + 11 < NCHUNK) LOAD_CHUNK(xD, tD, c + 11)
        COMPUTE_CHUNK(xE, tE_, c + 4)
        if (c + 12 < NCHUNK) LOAD_CHUNK(xE, tE_, c + 12)
        COMPUTE_CHUNK(xF, tF, c + 5)
        if (c + 13 < NCHUNK) LOAD_CHUNK(xF, tF, c + 13)
        COMPUTE_CHUNK(xG, tG, c + 6)
        if (c + 14 < NCHUNK) LOAD_CHUNK(xG, tG, c + 14)
        COMPUTE_CHUNK(xH, tH, c + 7)
    }
}

// ---------------------------------------------------------------------------
extern "C" void kernel_launch(void* const* d_in, const int* in_sizes, int n_in,
                              void* d_out, int out_size) {
    const float* tx = (const float*)d_in[0];   // [T, B, N]
    const float* TE = (const float*)d_in[1];   // [N, T]
    float* ty = (float*)d_out;                 // [T, B, N]
    (void)in_sizes; (void)n_in; (void)out_size;

    telif_kernel<<<BN / 64, 64>>>(tx, TE, ty);
}